// round 1
// baseline (speedup 1.0000x reference)
#include <cuda_runtime.h>
#include <cuda_bf16.h>
#include <math.h>

// Problem constants
#define B   64
#define S   128
#define H   1024
#define V   32000

// d_out layout: [output B*V | h_new B*H | attn_weights B*S]
#define OUT_SZ   (B * V)            // 2048000
#define HNEW_OFF (B * V)            // 2048000
#define ATTN_OFF (B * V + B * H)    // 2113536

// ---------------- device scratch (no runtime allocation allowed) ----------------
__device__ float g_gi[B * 3 * H];        // gi = x @ W_ih^T
__device__ float g_gh[B * 3 * H];        // gh = h @ W_hh^T
__device__ float g_v[B * H];             // v  = h_new @ attn_W
__device__ float g_concat_in[B * 2 * H]; // [h_new | context]
__device__ float g_concat_out[B * H];    // tanh(concat_in @ concat_W^T + b)

// ---------------- generic 64xN fp32 GEMM ----------------
// C[M=64, N] = act( A[64,K] @ W(^T) + bias )
// WTRANS=true : W is [N, K] row-major (C = A @ W^T)   -- NT
// WTRANS=false: W is [K, N] row-major (C = A @ W)     -- NN
// gather != nullptr: A row m is A[gather[m], :] (embedding lookup fusion)
#define TK 16
#define TN 64

template <int ACT, bool WTRANS>
__device__ __forceinline__ void gemm_body(
    const float* __restrict__ A, const int* __restrict__ gather,
    const float* __restrict__ W, const float* __restrict__ bias,
    float* __restrict__ C, int K, int N)
{
    __shared__ float As[TK][B + 4];   // +4 pad keeps float4 alignment, cuts conflicts
    __shared__ float Ws[TK][TN + 4];

    const int n0 = blockIdx.x * TN;
    const int t  = threadIdx.x;       // 256 threads
    const int tx = t & 15;            // n micro-tile
    const int ty = t >> 4;            // m micro-tile

    float acc[4][4] = {};

    for (int k0 = 0; k0 < K; k0 += TK) {
        // --- stage A tile: As[kk][m] = A[m, k0+kk] ---
        {
            const int row = t >> 2;         // 0..63
            const int q   = t & 3;          // quad of 4 k-values
            const float* Arow = gather ? (A + (size_t)gather[row] * K)
                                       : (A + (size_t)row * K);
            float4 v4 = *(const float4*)(Arow + k0 + q * 4);
            As[q * 4 + 0][row] = v4.x;
            As[q * 4 + 1][row] = v4.y;
            As[q * 4 + 2][row] = v4.z;
            As[q * 4 + 3][row] = v4.w;
        }
        // --- stage W tile: Ws[kk][n] ---
        if (WTRANS) {
            const int row = t >> 2;         // weight row n0+row
            const int q   = t & 3;
            float4 v4 = *(const float4*)(W + (size_t)(n0 + row) * K + k0 + q * 4);
            Ws[q * 4 + 0][row] = v4.x;
            Ws[q * 4 + 1][row] = v4.y;
            Ws[q * 4 + 2][row] = v4.z;
            Ws[q * 4 + 3][row] = v4.w;
        } else {
            const int kk = t >> 4;          // 0..15
            const int c  = t & 15;
            float4 v4 = *(const float4*)(W + (size_t)(k0 + kk) * N + n0 + c * 4);
            *(float4*)&Ws[kk][c * 4] = v4;
        }
        __syncthreads();

        #pragma unroll
        for (int kk = 0; kk < TK; kk++) {
            float4 a = *(const float4*)&As[kk][ty * 4];
            float4 w = *(const float4*)&Ws[kk][tx * 4];
            acc[0][0] += a.x * w.x; acc[0][1] += a.x * w.y; acc[0][2] += a.x * w.z; acc[0][3] += a.x * w.w;
            acc[1][0] += a.y * w.x; acc[1][1] += a.y * w.y; acc[1][2] += a.y * w.z; acc[1][3] += a.y * w.w;
            acc[2][0] += a.z * w.x; acc[2][1] += a.z * w.y; acc[2][2] += a.z * w.z; acc[2][3] += a.z * w.w;
            acc[3][0] += a.w * w.x; acc[3][1] += a.w * w.y; acc[3][2] += a.w * w.z; acc[3][3] += a.w * w.w;
        }
        __syncthreads();
    }

    #pragma unroll
    for (int i = 0; i < 4; i++) {
        const int m = ty * 4 + i;
        #pragma unroll
        for (int j = 0; j < 4; j++) {
            const int n = n0 + tx * 4 + j;
            float v = acc[i][j];
            if (bias) v += bias[n];
            if (ACT == 1) v = tanhf(v);
            C[(size_t)m * N + n] = v;
        }
    }
}

// GRU input/hidden GEMMs fused into one grid (gridDim = {48, 2})
__global__ void __launch_bounds__(256)
gru_gemm_kernel(const float* __restrict__ emb, const int* __restrict__ seq,
                const float* __restrict__ h,
                const float* __restrict__ Wih, const float* __restrict__ Whh)
{
    const float* A = blockIdx.y ? h : emb;
    const int* g   = blockIdx.y ? nullptr : seq;
    const float* W = blockIdx.y ? Whh : Wih;
    float* C       = blockIdx.y ? g_gh : g_gi;
    gemm_body<0, true>(A, g, W, nullptr, C, H, 3 * H);
}

template <int ACT>
__global__ void __launch_bounds__(256)
gemm_nt_kernel(const float* __restrict__ A, const float* __restrict__ W,
               const float* __restrict__ bias, float* __restrict__ C, int K, int N)
{
    gemm_body<ACT, true>(A, nullptr, W, bias, C, K, N);
}

__global__ void __launch_bounds__(256)
gemm_nn_kernel(const float* __restrict__ A, const float* __restrict__ W,
               float* __restrict__ C, int K, int N)
{
    gemm_body<0, false>(A, nullptr, W, nullptr, C, K, N);
}

// ---------------- GRU gate combination ----------------
__device__ __forceinline__ float sigmoidf_(float x) { return 1.f / (1.f + expf(-x)); }

__global__ void __launch_bounds__(256)
gru_gates_kernel(const float* __restrict__ bih, const float* __restrict__ bhh,
                 const float* __restrict__ h, float* __restrict__ hnew_out)
{
    const int idx = blockIdx.x * blockDim.x + threadIdx.x;  // b*H + k
    const int b = idx >> 10;
    const int k = idx & (H - 1);
    const float* gib = g_gi + (size_t)b * 3 * H;
    const float* ghb = g_gh + (size_t)b * 3 * H;

    float r = sigmoidf_((gib[k]         + bih[k])         + (ghb[k]         + bhh[k]));
    float z = sigmoidf_((gib[H + k]     + bih[H + k])     + (ghb[H + k]     + bhh[H + k]));
    float n = tanhf((gib[2 * H + k] + bih[2 * H + k]) + r * (ghb[2 * H + k] + bhh[2 * H + k]));
    float hv = h[idx];
    float hn = (1.f - z) * n + z * hv;

    hnew_out[idx] = hn;                         // h_new output (also GEMM input)
    g_concat_in[(size_t)b * 2 * H + k] = hn;    // left half of concat
}

// ---------------- attention: energies -> softmax -> context ----------------
// One block per batch element b. 256 threads.
__global__ void __launch_bounds__(256)
attn_kernel(const float* __restrict__ enc, float* __restrict__ attn_out)
{
    __shared__ float vs[H];
    __shared__ float es[S];

    const int b = blockIdx.x;
    const int t = threadIdx.x;
    const int warp = t >> 5, lane = t & 31;

    // v[b,:] into smem (256 float4s)
    ((float4*)vs)[t] = ((const float4*)(g_v + (size_t)b * H))[t];
    __syncthreads();

    // energies: warp w handles s = w*16 .. w*16+15, warp-wide fp32 dot of length 1024
    for (int si = 0; si < 16; si++) {
        const int s = warp * 16 + si;
        const float4* row = (const float4*)(enc + ((size_t)s * B + b) * H);
        float sum = 0.f;
        #pragma unroll
        for (int i = 0; i < 8; i++) {
            float4 e = row[lane + 32 * i];
            float4 v = ((const float4*)vs)[lane + 32 * i];
            sum += e.x * v.x + e.y * v.y + e.z * v.z + e.w * v.w;
        }
        #pragma unroll
        for (int o = 16; o; o >>= 1) sum += __shfl_xor_sync(0xFFFFFFFFu, sum, o);
        if (lane == 0) es[s] = sum;
    }
    __syncthreads();

    // softmax over S=128 (warp 0; 4 energies per lane)
    if (warp == 0) {
        float4 e4 = ((float4*)es)[lane];
        float m = fmaxf(fmaxf(e4.x, e4.y), fmaxf(e4.z, e4.w));
        #pragma unroll
        for (int o = 16; o; o >>= 1) m = fmaxf(m, __shfl_xor_sync(0xFFFFFFFFu, m, o));
        float4 x;
        x.x = expf(e4.x - m); x.y = expf(e4.y - m);
        x.z = expf(e4.z - m); x.w = expf(e4.w - m);
        float ss = x.x + x.y + x.z + x.w;
        #pragma unroll
        for (int o = 16; o; o >>= 1) ss += __shfl_xor_sync(0xFFFFFFFFu, ss, o);
        float inv = 1.f / ss;
        x.x *= inv; x.y *= inv; x.z *= inv; x.w *= inv;
        ((float4*)es)[lane] = x;                            // reuse as weights
        ((float4*)(attn_out + (size_t)b * S))[lane] = x;    // attn_weights output
    }
    __syncthreads();

    // context[b, h] = sum_s w[s] * enc[s,b,h]; thread t owns h = 4t..4t+3
    float4 acc = {0.f, 0.f, 0.f, 0.f};
    for (int s = 0; s < S; s++) {
        float w = es[s];
        float4 e = *(const float4*)(enc + ((size_t)s * B + b) * H + t * 4);
        acc.x += w * e.x; acc.y += w * e.y; acc.z += w * e.z; acc.w += w * e.w;
    }
    *(float4*)(g_concat_in + (size_t)b * 2 * H + H + t * 4) = acc;
}

// ---------------- launch ----------------
extern "C" void kernel_launch(void* const* d_in, const int* in_sizes, int n_in,
                              void* d_out, int out_size)
{
    const int*   seq   = (const int*)d_in[0];
    const float* h     = (const float*)d_in[1];   // [1,B,H]
    const float* enc   = (const float*)d_in[2];   // [S,B,H]
    const float* emb   = (const float*)d_in[3];   // [V,H]
    const float* Wih   = (const float*)d_in[4];   // [3H,H]
    const float* Whh   = (const float*)d_in[5];   // [3H,H]
    const float* bih   = (const float*)d_in[6];
    const float* bhh   = (const float*)d_in[7];
    const float* attnW = (const float*)d_in[8];   // [H,H]
    // d_in[9] = attn_b: constant per-b shift of energies -> cancels in softmax
    const float* catW  = (const float*)d_in[10];  // [H,2H]
    const float* catb  = (const float*)d_in[11];
    const float* outW  = (const float*)d_in[12];  // [V,H]
    const float* outb  = (const float*)d_in[13];

    float* out   = (float*)d_out;
    float* hnew  = out + HNEW_OFF;
    float* attnw = out + ATTN_OFF;

    // scratch addresses (host-side view of device symbols); cheap, graph-transparent
    float *p_v = nullptr, *p_cin = nullptr, *p_cout = nullptr;
    cudaGetSymbolAddress((void**)&p_v,    g_v);
    cudaGetSymbolAddress((void**)&p_cin,  g_concat_in);
    cudaGetSymbolAddress((void**)&p_cout, g_concat_out);

    // 1) GRU GEMMs: gi (gathered emb) and gh, fused grid
    gru_gemm_kernel<<<dim3(3 * H / TN, 2), 256>>>(emb, seq, h, Wih, Whh);

    // 2) gates -> h_new (into d_out) + left half of concat
    gru_gates_kernel<<<(B * H) / 256, 256>>>(bih, bhh, h, hnew);

    // 3) v = h_new @ attn_W   (NN)
    gemm_nn_kernel<<<H / TN, 256>>>(hnew, attnW, p_v, H, H);

    // 4) energies / softmax / context (attn_weights into d_out, context -> concat)
    attn_kernel<<<B, 256>>>(enc, attnw);

    // 5) concat_out = tanh(concat_in @ concat_W^T + concat_b)
    gemm_nt_kernel<1><<<H / TN, 256>>>(p_cin, catW, catb, p_cout, 2 * H, H);

    // 6) output = concat_out @ out_W^T + out_b   (the big one: N=32000)
    gemm_nt_kernel<0><<<V / TN, 256>>>(p_cout, outW, outb, out, H, V);
}

// round 2
// speedup vs baseline: 1.0777x; 1.0777x over previous
#include <cuda_runtime.h>
#include <cuda_bf16.h>
#include <math.h>

// Problem constants
#define B   64
#define S   128
#define H   1024
#define V   32000

// d_out layout: [output B*V | h_new B*H | attn_weights B*S]
#define HNEW_OFF (B * V)
#define ATTN_OFF (B * V + B * H)

typedef unsigned long long ull;

// ---------------- packed fp32x2 helpers (SASS FFMA2 path) ----------------
#define DUP2(d, x)      asm("mov.b64 %0, {%1, %1};" : "=l"(d) : "f"(x))
#define FFMA2(d, a, b)  asm("fma.rn.f32x2 %0, %1, %2, %0;" : "+l"(d) : "l"(a), "l"(b))
#define UNPK2(lo, hi, v) asm("mov.b64 {%0, %1}, %2;" : "=f"(lo), "=f"(hi) : "l"(v))

// ---------------- device scratch ----------------
__device__ float g_gi[B * 3 * H];
__device__ float g_gh[B * 3 * H];
__device__ float g_v[B * H];
__device__ float g_energies[B * S];
__device__ float g_concat_in[B * 2 * H];
__device__ float g_concat_out[B * H];

// ---------------- generic 64xN fp32 GEMM (f32x2-packed inner loop) ----------------
// C[64, N] = act( A[64,K] @ W(^T) + bias )
#define TK 16
#define TN 64
// As/Ws row stride must be a multiple of 4 floats (16B) for vector ld/st
#define APAD 4
#define WPAD 4

template <int ACT, bool WTRANS>
__device__ __forceinline__ void gemm_body(
    const float* __restrict__ A, const int* __restrict__ gather,
    const float* __restrict__ W, const float* __restrict__ bias,
    float* __restrict__ C, int K, int N)
{
    __shared__ float As[TK][B + APAD];   // stride 68 floats = 272B (16B multiple)
    __shared__ float Ws[TK][TN + WPAD];

    const int n0 = blockIdx.x * TN;
    const int t  = threadIdx.x;       // 256 threads
    const int tx = t & 15;            // n micro-tile index
    const int ty = t >> 4;            // m micro-tile index

    // acc2[i2][j]: m-pair (ty*4 + i2*2, +1) x n (tx*4 + j), packed fp32x2 along m
    ull acc2[2][4] = {};

    for (int k0 = 0; k0 < K; k0 += TK) {
        // stage A tile: As[kk][m]
        {
            const int row = t >> 2;         // 0..63
            const int q   = t & 3;
            const float* Arow = gather ? (A + (size_t)gather[row] * K)
                                       : (A + (size_t)row * K);
            float4 v4 = *(const float4*)(Arow + k0 + q * 4);
            As[q * 4 + 0][row] = v4.x;
            As[q * 4 + 1][row] = v4.y;
            As[q * 4 + 2][row] = v4.z;
            As[q * 4 + 3][row] = v4.w;
        }
        // stage W tile: Ws[kk][n]
        if (WTRANS) {
            const int row = t >> 2;
            const int q   = t & 3;
            float4 v4 = *(const float4*)(W + (size_t)(n0 + row) * K + k0 + q * 4);
            Ws[q * 4 + 0][row] = v4.x;
            Ws[q * 4 + 1][row] = v4.y;
            Ws[q * 4 + 2][row] = v4.z;
            Ws[q * 4 + 3][row] = v4.w;
        } else {
            const int kk = t >> 4;
            const int c  = t & 15;
            float4 v4 = *(const float4*)(W + (size_t)(k0 + kk) * N + n0 + c * 4);
            *(float4*)&Ws[kk][c * 4] = v4;
        }
        __syncthreads();

        #pragma unroll
        for (int kk = 0; kk < TK; kk++) {
            const ull* ap = (const ull*)&As[kk][ty * 4];   // 8B-aligned
            ull a01 = ap[0];
            ull a23 = ap[1];
            float4 w = *(const float4*)&Ws[kk][tx * 4];
            ull w0, w1, w2, w3;
            DUP2(w0, w.x); DUP2(w1, w.y); DUP2(w2, w.z); DUP2(w3, w.w);
            FFMA2(acc2[0][0], a01, w0); FFMA2(acc2[1][0], a23, w0);
            FFMA2(acc2[0][1], a01, w1); FFMA2(acc2[1][1], a23, w1);
            FFMA2(acc2[0][2], a01, w2); FFMA2(acc2[1][2], a23, w2);
            FFMA2(acc2[0][3], a01, w3); FFMA2(acc2[1][3], a23, w3);
        }
        __syncthreads();
    }

    #pragma unroll
    for (int i2 = 0; i2 < 2; i2++) {
        #pragma unroll
        for (int j = 0; j < 4; j++) {
            float lo, hi;
            UNPK2(lo, hi, acc2[i2][j]);
            const int n = n0 + tx * 4 + j;
            if (bias) { float bv = bias[n]; lo += bv; hi += bv; }
            if (ACT == 1) { lo = tanhf(lo); hi = tanhf(hi); }
            const int m = ty * 4 + i2 * 2;
            C[(size_t)m * N + n]       = lo;
            C[(size_t)(m + 1) * N + n] = hi;
        }
    }
}

// GRU input/hidden GEMMs fused into one grid (gridDim = {48, 2})
__global__ void __launch_bounds__(256)
gru_gemm_kernel(const float* __restrict__ emb, const int* __restrict__ seq,
                const float* __restrict__ h,
                const float* __restrict__ Wih, const float* __restrict__ Whh)
{
    const float* A = blockIdx.y ? h : emb;
    const int* g   = blockIdx.y ? nullptr : seq;
    const float* W = blockIdx.y ? Whh : Wih;
    float* C       = blockIdx.y ? g_gh : g_gi;
    gemm_body<0, true>(A, g, W, nullptr, C, H, 3 * H);
}

template <int ACT>
__global__ void __launch_bounds__(256)
gemm_nt_kernel(const float* __restrict__ A, const float* __restrict__ W,
               const float* __restrict__ bias, float* __restrict__ C, int K, int N)
{
    gemm_body<ACT, true>(A, nullptr, W, bias, C, K, N);
}

__global__ void __launch_bounds__(256)
gemm_nn_kernel(const float* __restrict__ A, const float* __restrict__ W,
               float* __restrict__ C, int K, int N)
{
    gemm_body<0, false>(A, nullptr, W, nullptr, C, K, N);
}

// ---------------- GRU gate combination ----------------
__device__ __forceinline__ float sigmoidf_(float x) { return 1.f / (1.f + expf(-x)); }

__global__ void __launch_bounds__(256)
gru_gates_kernel(const float* __restrict__ bih, const float* __restrict__ bhh,
                 const float* __restrict__ h, float* __restrict__ hnew_out)
{
    const int idx = blockIdx.x * blockDim.x + threadIdx.x;  // b*H + k
    const int b = idx >> 10;
    const int k = idx & (H - 1);
    const float* gib = g_gi + (size_t)b * 3 * H;
    const float* ghb = g_gh + (size_t)b * 3 * H;

    float r = sigmoidf_((gib[k]         + bih[k])         + (ghb[k]         + bhh[k]));
    float z = sigmoidf_((gib[H + k]     + bih[H + k])     + (ghb[H + k]     + bhh[H + k]));
    float n = tanhf((gib[2 * H + k] + bih[2 * H + k]) + r * (ghb[2 * H + k] + bhh[2 * H + k]));
    float hv = h[idx];
    float hn = (1.f - z) * n + z * hv;

    hnew_out[idx] = hn;
    g_concat_in[(size_t)b * 2 * H + k] = hn;
}

// ---------------- attention stage 1: energies ----------------
// grid (8, B): block computes 16 energies for batch b; warp w -> s = x*16 + w*2 + {0,1}
__global__ void __launch_bounds__(256)
energies_kernel(const float* __restrict__ enc)
{
    __shared__ float vs[H];
    const int b = blockIdx.y;
    const int t = threadIdx.x;
    const int warp = t >> 5, lane = t & 31;

    ((float4*)vs)[t] = ((const float4*)(g_v + (size_t)b * H))[t];
    __syncthreads();

    #pragma unroll
    for (int si = 0; si < 2; si++) {
        const int s = blockIdx.x * 16 + warp * 2 + si;
        const float4* row = (const float4*)(enc + ((size_t)s * B + b) * H);
        float sum = 0.f;
        #pragma unroll
        for (int i = 0; i < 8; i++) {
            float4 e = row[lane + 32 * i];
            float4 v = ((const float4*)vs)[lane + 32 * i];
            sum += e.x * v.x + e.y * v.y + e.z * v.z + e.w * v.w;
        }
        #pragma unroll
        for (int o = 16; o; o >>= 1) sum += __shfl_xor_sync(0xFFFFFFFFu, sum, o);
        if (lane == 0) g_energies[b * S + s] = sum;
    }
}

// ---------------- attention stage 2: softmax + context ----------------
// grid (4, B): block handles h = x*256 .. x*256+255 for batch b; softmax recomputed per block
__global__ void __launch_bounds__(256)
context_kernel(const float* __restrict__ enc, float* __restrict__ attn_out)
{
    __shared__ float ws[S];
    const int b = blockIdx.y;
    const int t = threadIdx.x;
    const int warp = t >> 5, lane = t & 31;

    if (warp == 0) {
        float4 e4 = ((const float4*)(g_energies + b * S))[lane];
        float m = fmaxf(fmaxf(e4.x, e4.y), fmaxf(e4.z, e4.w));
        #pragma unroll
        for (int o = 16; o; o >>= 1) m = fmaxf(m, __shfl_xor_sync(0xFFFFFFFFu, m, o));
        float4 x;
        x.x = expf(e4.x - m); x.y = expf(e4.y - m);
        x.z = expf(e4.z - m); x.w = expf(e4.w - m);
        float ss = x.x + x.y + x.z + x.w;
        #pragma unroll
        for (int o = 16; o; o >>= 1) ss += __shfl_xor_sync(0xFFFFFFFFu, ss, o);
        float inv = 1.f / ss;
        x.x *= inv; x.y *= inv; x.z *= inv; x.w *= inv;
        ((float4*)ws)[lane] = x;
        if (blockIdx.x == 0)
            ((float4*)(attn_out + (size_t)b * S))[lane] = x;
    }
    __syncthreads();

    const int h = blockIdx.x * 256 + t;
    const float* ep = enc + (size_t)b * H + h;
    float acc0 = 0.f, acc1 = 0.f, acc2 = 0.f, acc3 = 0.f;
    #pragma unroll 4
    for (int s = 0; s < S; s += 4) {
        acc0 += ws[s]     * ep[(size_t)(s)     * B * H];
        acc1 += ws[s + 1] * ep[(size_t)(s + 1) * B * H];
        acc2 += ws[s + 2] * ep[(size_t)(s + 2) * B * H];
        acc3 += ws[s + 3] * ep[(size_t)(s + 3) * B * H];
    }
    g_concat_in[(size_t)b * 2 * H + H + h] = (acc0 + acc1) + (acc2 + acc3);
}

// ---------------- launch ----------------
extern "C" void kernel_launch(void* const* d_in, const int* in_sizes, int n_in,
                              void* d_out, int out_size)
{
    const int*   seq   = (const int*)d_in[0];
    const float* h     = (const float*)d_in[1];
    const float* enc   = (const float*)d_in[2];
    const float* emb   = (const float*)d_in[3];
    const float* Wih   = (const float*)d_in[4];
    const float* Whh   = (const float*)d_in[5];
    const float* bih   = (const float*)d_in[6];
    const float* bhh   = (const float*)d_in[7];
    const float* attnW = (const float*)d_in[8];
    // d_in[9] = attn_b: cancels in softmax (and is zero)
    const float* catW  = (const float*)d_in[10];
    const float* catb  = (const float*)d_in[11];
    const float* outW  = (const float*)d_in[12];
    const float* outb  = (const float*)d_in[13];

    float* out   = (float*)d_out;
    float* hnew  = out + HNEW_OFF;
    float* attnw = out + ATTN_OFF;

    float *p_v = nullptr, *p_cin = nullptr, *p_cout = nullptr;
    cudaGetSymbolAddress((void**)&p_v,    g_v);
    cudaGetSymbolAddress((void**)&p_cin,  g_concat_in);
    cudaGetSymbolAddress((void**)&p_cout, g_concat_out);

    // 1) GRU GEMMs
    gru_gemm_kernel<<<dim3(3 * H / TN, 2), 256>>>(emb, seq, h, Wih, Whh);
    // 2) gates -> h_new
    gru_gates_kernel<<<(B * H) / 256, 256>>>(bih, bhh, h, hnew);
    // 3) v = h_new @ attn_W
    gemm_nn_kernel<<<H / TN, 256>>>(hnew, attnW, p_v, H, H);
    // 4) energies
    energies_kernel<<<dim3(8, B), 256>>>(enc);
    // 5) softmax + context
    context_kernel<<<dim3(4, B), 256>>>(enc, attnw);
    // 6) concat_out = tanh(...)
    gemm_nt_kernel<1><<<H / TN, 256>>>(p_cin, catW, catb, p_cout, 2 * H, H);
    // 7) output (the big one)
    gemm_nt_kernel<0><<<V / TN, 256>>>(p_cout, outW, outb, out, H, V);
}

// round 3
// speedup vs baseline: 2.0475x; 1.8999x over previous
#include <cuda_runtime.h>
#include <math.h>

#define B 64
#define S 128
#define H 1024
#define V 32000

#define HNEW_OFF (B * V)
#define ATTN_OFF (B * V + B * H)

typedef unsigned long long ull;

// ---------------- packed fp32x2 (FFMA2) helpers ----------------
#define DUP2(d, x)       asm("mov.b64 %0, {%1, %1};" : "=l"(d) : "f"(x))
#define FFMA2(d, a, b)   asm("fma.rn.f32x2 %0, %1, %2, %0;" : "+l"(d) : "l"(a), "l"(b))
#define UNPK2(lo, hi, v) asm("mov.b64 {%0, %1}, %2;" : "=f"(lo), "=f"(hi) : "l"(v))

// ---------------- device scratch ----------------
__device__ float g_gipart[4][B * 3 * H];
__device__ float g_ghpart[4][B * 3 * H];
__device__ float g_vpart[8][B * H];
__device__ float g_cpart[8][B * H];
__device__ float g_energies[B * S];
__device__ float g_concat_in[B * 2 * H];
__device__ float g_concat_out[B * H];

// ---------------- pipelined 64x128 SGEMM body ----------------
// C[64, N](tile n0..n0+127) += A[64, kb:ke] @ W(^T)
// WTRANS: W[N,K] row-major (NT). !WTRANS: W[K,N] row-major (NN).
// bias/ACT applied only by callers with a single K split.
#define TKK 16
#define TNN 128

template <int ACT, bool WTRANS>
__device__ __forceinline__ void gemm_pipe_body(
    const float* __restrict__ A, const int* __restrict__ gather,
    const float* __restrict__ W, const float* __restrict__ bias,
    float* __restrict__ C, int K, int N, int kb, int ke)
{
    __shared__ __align__(16) float As[2][TKK][64];
    __shared__ __align__(16) float Ws[2][TKK][TNN];

    const int n0  = blockIdx.x * TNN;
    const int t   = threadIdx.x;          // 128 threads
    const int txn = t & 15;               // n-group (8 cols each)
    const int tym = t >> 4;               // m-group (8 rows each)

    // A staging map: row = t>>1 (0..63), k-quad base = (t&1)*8
    const int arow = t >> 1;
    const int akq  = (t & 1) * 8;
    const float* Arow = (gather ? (A + (size_t)gather[arow] * K)
                                : (A + (size_t)arow * K)) + akq;

    // W staging map
    const float* Wp;
    int wkk = 0, wcb = 0;
    if (WTRANS) {
        Wp = W + (size_t)(n0 + t) * K;            // row n0+t, 16 k per iter
    } else {
        wkk = t >> 3;                              // 0..15
        wcb = (t & 7) * 16;                        // 0..112
        Wp = W + (size_t)wkk * N + n0 + wcb;       // 4 float4 per iter
    }

    ull acc[4][8];
    #pragma unroll
    for (int p = 0; p < 4; p++)
        #pragma unroll
        for (int j = 0; j < 8; j++) acc[p][j] = 0ULL;

    float4 pa0, pa1, pw0, pw1, pw2, pw3;

    // ---- prefetch tile 0 ----
    {
        const float* ap = Arow + kb;
        pa0 = *(const float4*)(ap);
        pa1 = *(const float4*)(ap + 4);
        if (WTRANS) {
            const float* wp = Wp + kb;
            pw0 = *(const float4*)(wp);      pw1 = *(const float4*)(wp + 4);
            pw2 = *(const float4*)(wp + 8);  pw3 = *(const float4*)(wp + 12);
        } else {
            const float* wp = Wp + (size_t)kb * N;
            pw0 = *(const float4*)(wp);      pw1 = *(const float4*)(wp + 4);
            pw2 = *(const float4*)(wp + 8);  pw3 = *(const float4*)(wp + 12);
        }
    }

    const int nIter = (ke - kb) / TKK;
    int buf = 0;
    for (int it = 0; it < nIter; it++) {
        // ---- store prefetched tile into smem buffer `buf` ----
        {
            float* ad = &As[buf][0][0];
            ad[(akq + 0) * 64 + arow] = pa0.x;
            ad[(akq + 1) * 64 + arow] = pa0.y;
            ad[(akq + 2) * 64 + arow] = pa0.z;
            ad[(akq + 3) * 64 + arow] = pa0.w;
            ad[(akq + 4) * 64 + arow] = pa1.x;
            ad[(akq + 5) * 64 + arow] = pa1.y;
            ad[(akq + 6) * 64 + arow] = pa1.z;
            ad[(akq + 7) * 64 + arow] = pa1.w;
            if (WTRANS) {
                float* wd = &Ws[buf][0][0];
                wd[ 0 * TNN + t] = pw0.x;  wd[ 1 * TNN + t] = pw0.y;
                wd[ 2 * TNN + t] = pw0.z;  wd[ 3 * TNN + t] = pw0.w;
                wd[ 4 * TNN + t] = pw1.x;  wd[ 5 * TNN + t] = pw1.y;
                wd[ 6 * TNN + t] = pw1.z;  wd[ 7 * TNN + t] = pw1.w;
                wd[ 8 * TNN + t] = pw2.x;  wd[ 9 * TNN + t] = pw2.y;
                wd[10 * TNN + t] = pw2.z;  wd[11 * TNN + t] = pw2.w;
                wd[12 * TNN + t] = pw3.x;  wd[13 * TNN + t] = pw3.y;
                wd[14 * TNN + t] = pw3.z;  wd[15 * TNN + t] = pw3.w;
            } else {
                *(float4*)&Ws[buf][wkk][wcb +  0] = pw0;
                *(float4*)&Ws[buf][wkk][wcb +  4] = pw1;
                *(float4*)&Ws[buf][wkk][wcb +  8] = pw2;
                *(float4*)&Ws[buf][wkk][wcb + 12] = pw3;
            }
        }
        __syncthreads();

        // ---- issue LDG for next tile (hidden behind compute) ----
        if (it + 1 < nIter) {
            const int k0 = kb + (it + 1) * TKK;
            const float* ap = Arow + k0;
            pa0 = *(const float4*)(ap);
            pa1 = *(const float4*)(ap + 4);
            if (WTRANS) {
                const float* wp = Wp + k0;
                pw0 = *(const float4*)(wp);      pw1 = *(const float4*)(wp + 4);
                pw2 = *(const float4*)(wp + 8);  pw3 = *(const float4*)(wp + 12);
            } else {
                const float* wp = Wp + (size_t)k0 * N;
                pw0 = *(const float4*)(wp);      pw1 = *(const float4*)(wp + 4);
                pw2 = *(const float4*)(wp + 8);  pw3 = *(const float4*)(wp + 12);
            }
        }

        // ---- compute on buffer `buf` ----
        #pragma unroll
        for (int kk = 0; kk < TKK; kk++) {
            ulonglong2 aa = *(const ulonglong2*)&As[buf][kk][tym * 8];
            ulonglong2 ab = *(const ulonglong2*)&As[buf][kk][tym * 8 + 4];
            float4 wlo = *(const float4*)&Ws[buf][kk][txn * 8];
            float4 whi = *(const float4*)&Ws[buf][kk][txn * 8 + 4];
            ull w0, w1, w2, w3, w4, w5, w6, w7;
            DUP2(w0, wlo.x); DUP2(w1, wlo.y); DUP2(w2, wlo.z); DUP2(w3, wlo.w);
            DUP2(w4, whi.x); DUP2(w5, whi.y); DUP2(w6, whi.z); DUP2(w7, whi.w);
            FFMA2(acc[0][0], aa.x, w0); FFMA2(acc[1][0], aa.y, w0);
            FFMA2(acc[2][0], ab.x, w0); FFMA2(acc[3][0], ab.y, w0);
            FFMA2(acc[0][1], aa.x, w1); FFMA2(acc[1][1], aa.y, w1);
            FFMA2(acc[2][1], ab.x, w1); FFMA2(acc[3][1], ab.y, w1);
            FFMA2(acc[0][2], aa.x, w2); FFMA2(acc[1][2], aa.y, w2);
            FFMA2(acc[2][2], ab.x, w2); FFMA2(acc[3][2], ab.y, w2);
            FFMA2(acc[0][3], aa.x, w3); FFMA2(acc[1][3], aa.y, w3);
            FFMA2(acc[2][3], ab.x, w3); FFMA2(acc[3][3], ab.y, w3);
            FFMA2(acc[0][4], aa.x, w4); FFMA2(acc[1][4], aa.y, w4);
            FFMA2(acc[2][4], ab.x, w4); FFMA2(acc[3][4], ab.y, w4);
            FFMA2(acc[0][5], aa.x, w5); FFMA2(acc[1][5], aa.y, w5);
            FFMA2(acc[2][5], ab.x, w5); FFMA2(acc[3][5], ab.y, w5);
            FFMA2(acc[0][6], aa.x, w6); FFMA2(acc[1][6], aa.y, w6);
            FFMA2(acc[2][6], ab.x, w6); FFMA2(acc[3][6], ab.y, w6);
            FFMA2(acc[0][7], aa.x, w7); FFMA2(acc[1][7], aa.y, w7);
            FFMA2(acc[2][7], ab.x, w7); FFMA2(acc[3][7], ab.y, w7);
        }
        __syncthreads();
        buf ^= 1;
    }

    // ---- epilogue ----
    float bv[8];
    if (bias) {
        float4 b0 = *(const float4*)(bias + n0 + txn * 8);
        float4 b1 = *(const float4*)(bias + n0 + txn * 8 + 4);
        bv[0] = b0.x; bv[1] = b0.y; bv[2] = b0.z; bv[3] = b0.w;
        bv[4] = b1.x; bv[5] = b1.y; bv[6] = b1.z; bv[7] = b1.w;
    }
    #pragma unroll
    for (int p = 0; p < 4; p++) {
        float lo[8], hi[8];
        #pragma unroll
        for (int j = 0; j < 8; j++) {
            UNPK2(lo[j], hi[j], acc[p][j]);
            if (bias) { lo[j] += bv[j]; hi[j] += bv[j]; }
            if (ACT == 1) { lo[j] = tanhf(lo[j]); hi[j] = tanhf(hi[j]); }
        }
        const int m = tym * 8 + p * 2;
        float* c0 = C + (size_t)m * N + n0 + txn * 8;
        float* c1 = c0 + N;
        float4 s;
        s.x = lo[0]; s.y = lo[1]; s.z = lo[2]; s.w = lo[3]; *(float4*)(c0)     = s;
        s.x = lo[4]; s.y = lo[5]; s.z = lo[6]; s.w = lo[7]; *(float4*)(c0 + 4) = s;
        s.x = hi[0]; s.y = hi[1]; s.z = hi[2]; s.w = hi[3]; *(float4*)(c1)     = s;
        s.x = hi[4]; s.y = hi[5]; s.z = hi[6]; s.w = hi[7]; *(float4*)(c1 + 4) = s;
    }
}

// ---------------- GEMM wrappers ----------------
// GRU: gridDim = (3072/128=24, 2 {gi,gh}, 4 splits of K=256)
__global__ void __launch_bounds__(128)
k_gru_gemm(const float* __restrict__ emb, const int* __restrict__ seq,
           const float* __restrict__ h,
           const float* __restrict__ Wih, const float* __restrict__ Whh)
{
    const int z = blockIdx.z;
    const int kb = z * 256, ke = kb + 256;
    if (blockIdx.y == 0)
        gemm_pipe_body<0, true>(emb, seq, Wih, nullptr, g_gipart[z], H, 3 * H, kb, ke);
    else
        gemm_pipe_body<0, true>(h, nullptr, Whh, nullptr, g_ghpart[z], H, 3 * H, kb, ke);
}

// v = h_new @ attn_W (NN). gridDim = (8, 1, 8 splits of K=128)
__global__ void __launch_bounds__(128)
k_v_gemm(const float* __restrict__ hnew, const float* __restrict__ attnW)
{
    const int z = blockIdx.z;
    gemm_pipe_body<0, false>(hnew, nullptr, attnW, nullptr, g_vpart[z],
                             H, H, z * 128, z * 128 + 128);
}

// concat partial: g_cpart[z] = concat_in @ concat_W^T (K=2048). grid (8,1,8)
__global__ void __launch_bounds__(128)
k_concat_gemm(const float* __restrict__ catW)
{
    const int z = blockIdx.z;
    gemm_pipe_body<0, true>(g_concat_in, nullptr, catW, nullptr, g_cpart[z],
                            2 * H, H, z * 256, z * 256 + 256);
}

// out = concat_out @ out_W^T + out_b. grid (250,1,1), single split
__global__ void __launch_bounds__(128)
k_out_gemm(const float* __restrict__ outW, const float* __restrict__ outb,
           float* __restrict__ out)
{
    gemm_pipe_body<0, true>(g_concat_out, nullptr, outW, outb, out, H, V, 0, H);
}

// ---------------- GRU gates (sums 4 K-splits) ----------------
__device__ __forceinline__ float sigmoidf_(float x) { return 1.f / (1.f + expf(-x)); }

__global__ void __launch_bounds__(256)
gru_gates_kernel(const float* __restrict__ bih, const float* __restrict__ bhh,
                 const float* __restrict__ h, float* __restrict__ hnew_out)
{
    const int idx = blockIdx.x * blockDim.x + threadIdx.x;  // b*H + k
    const int b = idx >> 10;
    const int k = idx & (H - 1);
    const size_t o = (size_t)b * 3 * H;

    float gir = 0.f, giz = 0.f, gin = 0.f, ghr = 0.f, ghz = 0.f, ghn = 0.f;
    #pragma unroll
    for (int s = 0; s < 4; s++) {
        const float* gp = g_gipart[s] + o;
        const float* hp = g_ghpart[s] + o;
        gir += gp[k];         ghr += hp[k];
        giz += gp[H + k];     ghz += hp[H + k];
        gin += gp[2 * H + k]; ghn += hp[2 * H + k];
    }
    float r = sigmoidf_((gir + bih[k])         + (ghr + bhh[k]));
    float z = sigmoidf_((giz + bih[H + k])     + (ghz + bhh[H + k]));
    float n = tanhf((gin + bih[2 * H + k]) + r * (ghn + bhh[2 * H + k]));
    float hv = h[idx];
    float hn = (1.f - z) * n + z * hv;

    hnew_out[idx] = hn;
    g_concat_in[(size_t)b * 2 * H + k] = hn;
}

// ---------------- attention stage 1: energies (sums 8 v-splits) ----------------
__global__ void __launch_bounds__(256)
energies_kernel(const float* __restrict__ enc)
{
    __shared__ float vs[H];
    const int b = blockIdx.y;
    const int t = threadIdx.x;
    const int warp = t >> 5, lane = t & 31;

    float4 a = {0.f, 0.f, 0.f, 0.f};
    #pragma unroll
    for (int s = 0; s < 8; s++) {
        float4 p = ((const float4*)(g_vpart[s] + (size_t)b * H))[t];
        a.x += p.x; a.y += p.y; a.z += p.z; a.w += p.w;
    }
    ((float4*)vs)[t] = a;
    __syncthreads();

    #pragma unroll
    for (int si = 0; si < 2; si++) {
        const int s = blockIdx.x * 16 + warp * 2 + si;
        const float4* row = (const float4*)(enc + ((size_t)s * B + b) * H);
        float sum = 0.f;
        #pragma unroll
        for (int i = 0; i < 8; i++) {
            float4 e = row[lane + 32 * i];
            float4 v = ((const float4*)vs)[lane + 32 * i];
            sum += e.x * v.x + e.y * v.y + e.z * v.z + e.w * v.w;
        }
        #pragma unroll
        for (int o = 16; o; o >>= 1) sum += __shfl_xor_sync(0xFFFFFFFFu, sum, o);
        if (lane == 0) g_energies[b * S + s] = sum;
    }
}

// ---------------- attention stage 2: softmax + context ----------------
__global__ void __launch_bounds__(256)
context_kernel(const float* __restrict__ enc, float* __restrict__ attn_out)
{
    __shared__ float ws[S];
    const int b = blockIdx.y;
    const int t = threadIdx.x;
    const int warp = t >> 5, lane = t & 31;

    if (warp == 0) {
        float4 e4 = ((const float4*)(g_energies + b * S))[lane];
        float m = fmaxf(fmaxf(e4.x, e4.y), fmaxf(e4.z, e4.w));
        #pragma unroll
        for (int o = 16; o; o >>= 1) m = fmaxf(m, __shfl_xor_sync(0xFFFFFFFFu, m, o));
        float4 x;
        x.x = expf(e4.x - m); x.y = expf(e4.y - m);
        x.z = expf(e4.z - m); x.w = expf(e4.w - m);
        float ss = x.x + x.y + x.z + x.w;
        #pragma unroll
        for (int o = 16; o; o >>= 1) ss += __shfl_xor_sync(0xFFFFFFFFu, ss, o);
        float inv = 1.f / ss;
        x.x *= inv; x.y *= inv; x.z *= inv; x.w *= inv;
        ((float4*)ws)[lane] = x;
        if (blockIdx.x == 0)
            ((float4*)(attn_out + (size_t)b * S))[lane] = x;
    }
    __syncthreads();

    const int h = blockIdx.x * 256 + t;
    const float* ep = enc + (size_t)b * H + h;
    float a0 = 0.f, a1 = 0.f, a2 = 0.f, a3 = 0.f;
    #pragma unroll 4
    for (int s = 0; s < S; s += 4) {
        a0 += ws[s]     * ep[(size_t)(s)     * B * H];
        a1 += ws[s + 1] * ep[(size_t)(s + 1) * B * H];
        a2 += ws[s + 2] * ep[(size_t)(s + 2) * B * H];
        a3 += ws[s + 3] * ep[(size_t)(s + 3) * B * H];
    }
    g_concat_in[(size_t)b * 2 * H + H + h] = (a0 + a1) + (a2 + a3);
}

// ---------------- concat reduce: tanh(sum_splits + bias) ----------------
__global__ void __launch_bounds__(256)
concat_reduce_kernel(const float* __restrict__ catb)
{
    const int idx = blockIdx.x * blockDim.x + threadIdx.x;  // b*H + k
    const int k = idx & (H - 1);
    float s = 0.f;
    #pragma unroll
    for (int p = 0; p < 8; p++) s += g_cpart[p][idx];
    g_concat_out[idx] = tanhf(s + catb[k]);
}

// ---------------- launch ----------------
extern "C" void kernel_launch(void* const* d_in, const int* in_sizes, int n_in,
                              void* d_out, int out_size)
{
    const int*   seq   = (const int*)d_in[0];
    const float* h     = (const float*)d_in[1];
    const float* enc   = (const float*)d_in[2];
    const float* emb   = (const float*)d_in[3];
    const float* Wih   = (const float*)d_in[4];
    const float* Whh   = (const float*)d_in[5];
    const float* bih   = (const float*)d_in[6];
    const float* bhh   = (const float*)d_in[7];
    const float* attnW = (const float*)d_in[8];
    // d_in[9] = attn_b: constant across s -> cancels in softmax (and is zero)
    const float* catW  = (const float*)d_in[10];
    const float* catb  = (const float*)d_in[11];
    const float* outW  = (const float*)d_in[12];
    const float* outb  = (const float*)d_in[13];

    float* out   = (float*)d_out;
    float* hnew  = out + HNEW_OFF;
    float* attnw = out + ATTN_OFF;

    // 1) GRU GEMMs, split-K x4  (24 x 2 x 4 = 192 blocks)
    k_gru_gemm<<<dim3(3 * H / TNN, 2, 4), 128>>>(emb, seq, h, Wih, Whh);
    // 2) gates: sum splits -> h_new (d_out) + concat left half
    gru_gates_kernel<<<(B * H) / 256, 256>>>(bih, bhh, h, hnew);
    // 3) v = h_new @ attn_W, split-K x8 (64 blocks)
    k_v_gemm<<<dim3(H / TNN, 1, 8), 128>>>(hnew, attnW);
    // 4) energies (sums v splits)
    energies_kernel<<<dim3(8, B), 256>>>(enc);
    // 5) softmax + context
    context_kernel<<<dim3(4, B), 256>>>(enc, attnw);
    // 6) concat GEMM, split-K x8 (64 blocks)
    k_concat_gemm<<<dim3(H / TNN, 1, 8), 128>>>(catW);
    // 7) reduce + bias + tanh
    concat_reduce_kernel<<<(B * H) / 256, 256>>>(catb);
    // 8) out GEMM (250 blocks)
    k_out_gemm<<<V / TNN, 128>>>(outW, outb, out);
}

// round 4
// speedup vs baseline: 2.4089x; 1.1765x over previous
#include <cuda_runtime.h>
#include <math.h>

#define B 64
#define S 128
#define H 1024
#define V 32000

#define HNEW_OFF (B * V)
#define ATTN_OFF (B * V + B * H)

typedef unsigned long long ull;

// ---------------- packed fp32x2 (FFMA2) helpers ----------------
#define DUP2(d, x)       asm("mov.b64 %0, {%1, %1};" : "=l"(d) : "f"(x))
#define FFMA2(d, a, b)   asm("fma.rn.f32x2 %0, %1, %2, %0;" : "+l"(d) : "l"(a), "l"(b))
#define UNPK2(lo, hi, v) asm("mov.b64 {%0, %1}, %2;" : "=f"(lo), "=f"(hi) : "l"(v))

// ---------------- device scratch ----------------
__device__ float g_gipart[4][B * 3 * H];
__device__ float g_ghpart[4][B * 3 * H];
__device__ float g_vpart[8][B * H];
__device__ float g_cpart[8][B * H];
__device__ float g_energies[B * S];
__device__ float g_concat_in[B * 2 * H];
__device__ float g_concat_out[B * H];

// ---------------- pipelined 64x128 SGEMM body ----------------
// C[64, N](tile n0..n0+127) = A[64, kb:ke] @ W(^T)  (+bias, ACT on full-K callers)
// Thread micro-tile: 8 m-rows (tym*8..+7) x 8 n-cols split as
//   {n0 + txn*4 .. +3} U {n0 + 64 + txn*4 .. +3}   (conflict-free LDS)
#define TKK 16
#define TNN 128

template <int ACT, bool WTRANS>
__device__ __forceinline__ void gemm_pipe_body(
    const float* __restrict__ A, const int* __restrict__ gather,
    const float* __restrict__ W, const float* __restrict__ bias,
    float* __restrict__ C, int K, int N, int kb, int ke)
{
    __shared__ __align__(16) float As[2][TKK][64];
    __shared__ __align__(16) float Ws[2][TKK][TNN];

    const int n0  = blockIdx.x * TNN;
    const int t   = threadIdx.x;          // 128 threads
    const int txn = t & 15;               // n-group
    const int tym = t >> 4;               // m-group (8 rows)

    // A staging: row = t>>1 (0..63), k-quad base = (t&1)*8
    const int arow = t >> 1;
    const int akq  = (t & 1) * 8;
    const float* Arow = (gather ? (A + (size_t)gather[arow] * K)
                                : (A + (size_t)arow * K)) + akq;

    // W staging map
    const float* Wp;
    int wkk = 0, wcb = 0;
    if (WTRANS) {
        Wp = W + (size_t)(n0 + t) * K;            // row n0+t, 16 k per iter
    } else {
        wkk = t >> 3;                              // 0..15
        wcb = (t & 7) * 16;                        // 0..112
        Wp = W + (size_t)wkk * N + n0 + wcb;
    }

    // acc[p][j]: m-pair (tym*8 + p*2, +1) x n-col j (j<4: txn*4+j ; j>=4: 64+txn*4+j-4)
    ull acc[4][8];
    #pragma unroll
    for (int p = 0; p < 4; p++)
        #pragma unroll
        for (int j = 0; j < 8; j++) acc[p][j] = 0ULL;

    float4 pa0, pa1, pw0, pw1, pw2, pw3;

    // ---- prefetch tile 0 + store to buf 0 ----
    {
        const float* ap = Arow + kb;
        pa0 = *(const float4*)(ap);
        pa1 = *(const float4*)(ap + 4);
        if (WTRANS) {
            const float* wp = Wp + kb;
            pw0 = *(const float4*)(wp);      pw1 = *(const float4*)(wp + 4);
            pw2 = *(const float4*)(wp + 8);  pw3 = *(const float4*)(wp + 12);
        } else {
            const float* wp = Wp + (size_t)kb * N;
            pw0 = *(const float4*)(wp);      pw1 = *(const float4*)(wp + 4);
            pw2 = *(const float4*)(wp + 8);  pw3 = *(const float4*)(wp + 12);
        }
        float* ad = &As[0][0][0];
        ad[(akq + 0) * 64 + arow] = pa0.x; ad[(akq + 1) * 64 + arow] = pa0.y;
        ad[(akq + 2) * 64 + arow] = pa0.z; ad[(akq + 3) * 64 + arow] = pa0.w;
        ad[(akq + 4) * 64 + arow] = pa1.x; ad[(akq + 5) * 64 + arow] = pa1.y;
        ad[(akq + 6) * 64 + arow] = pa1.z; ad[(akq + 7) * 64 + arow] = pa1.w;
        if (WTRANS) {
            float* wd = &Ws[0][0][0];
            wd[ 0 * TNN + t] = pw0.x;  wd[ 1 * TNN + t] = pw0.y;
            wd[ 2 * TNN + t] = pw0.z;  wd[ 3 * TNN + t] = pw0.w;
            wd[ 4 * TNN + t] = pw1.x;  wd[ 5 * TNN + t] = pw1.y;
            wd[ 6 * TNN + t] = pw1.z;  wd[ 7 * TNN + t] = pw1.w;
            wd[ 8 * TNN + t] = pw2.x;  wd[ 9 * TNN + t] = pw2.y;
            wd[10 * TNN + t] = pw2.z;  wd[11 * TNN + t] = pw2.w;
            wd[12 * TNN + t] = pw3.x;  wd[13 * TNN + t] = pw3.y;
            wd[14 * TNN + t] = pw3.z;  wd[15 * TNN + t] = pw3.w;
        } else {
            *(float4*)&Ws[0][wkk][wcb +  0] = pw0;
            *(float4*)&Ws[0][wkk][wcb +  4] = pw1;
            *(float4*)&Ws[0][wkk][wcb +  8] = pw2;
            *(float4*)&Ws[0][wkk][wcb + 12] = pw3;
        }
    }
    __syncthreads();

    const int nIter = (ke - kb) / TKK;
    int buf = 0;
    for (int it = 0; it < nIter; it++) {
        const bool more = (it + 1 < nIter);
        // ---- LDG next tile into regs (latency hidden by compute below) ----
        if (more) {
            const int k0 = kb + (it + 1) * TKK;
            const float* ap = Arow + k0;
            pa0 = *(const float4*)(ap);
            pa1 = *(const float4*)(ap + 4);
            if (WTRANS) {
                const float* wp = Wp + k0;
                pw0 = *(const float4*)(wp);      pw1 = *(const float4*)(wp + 4);
                pw2 = *(const float4*)(wp + 8);  pw3 = *(const float4*)(wp + 12);
            } else {
                const float* wp = Wp + (size_t)k0 * N;
                pw0 = *(const float4*)(wp);      pw1 = *(const float4*)(wp + 4);
                pw2 = *(const float4*)(wp + 8);  pw3 = *(const float4*)(wp + 12);
            }
        }

        // ---- compute on buffer `buf` (conflict-free LDS) ----
        #pragma unroll
        for (int kk = 0; kk < TKK; kk++) {
            ulonglong2 aa = *(const ulonglong2*)&As[buf][kk][tym * 8];
            ulonglong2 ab = *(const ulonglong2*)&As[buf][kk][tym * 8 + 4];
            float4 wlo = *(const float4*)&Ws[buf][kk][txn * 4];
            float4 whi = *(const float4*)&Ws[buf][kk][64 + txn * 4];
            ull w0, w1, w2, w3, w4, w5, w6, w7;
            DUP2(w0, wlo.x); DUP2(w1, wlo.y); DUP2(w2, wlo.z); DUP2(w3, wlo.w);
            DUP2(w4, whi.x); DUP2(w5, whi.y); DUP2(w6, whi.z); DUP2(w7, whi.w);
            FFMA2(acc[0][0], aa.x, w0); FFMA2(acc[1][0], aa.y, w0);
            FFMA2(acc[2][0], ab.x, w0); FFMA2(acc[3][0], ab.y, w0);
            FFMA2(acc[0][1], aa.x, w1); FFMA2(acc[1][1], aa.y, w1);
            FFMA2(acc[2][1], ab.x, w1); FFMA2(acc[3][1], ab.y, w1);
            FFMA2(acc[0][2], aa.x, w2); FFMA2(acc[1][2], aa.y, w2);
            FFMA2(acc[2][2], ab.x, w2); FFMA2(acc[3][2], ab.y, w2);
            FFMA2(acc[0][3], aa.x, w3); FFMA2(acc[1][3], aa.y, w3);
            FFMA2(acc[2][3], ab.x, w3); FFMA2(acc[3][3], ab.y, w3);
            FFMA2(acc[0][4], aa.x, w4); FFMA2(acc[1][4], aa.y, w4);
            FFMA2(acc[2][4], ab.x, w4); FFMA2(acc[3][4], ab.y, w4);
            FFMA2(acc[0][5], aa.x, w5); FFMA2(acc[1][5], aa.y, w5);
            FFMA2(acc[2][5], ab.x, w5); FFMA2(acc[3][5], ab.y, w5);
            FFMA2(acc[0][6], aa.x, w6); FFMA2(acc[1][6], aa.y, w6);
            FFMA2(acc[2][6], ab.x, w6); FFMA2(acc[3][6], ab.y, w6);
            FFMA2(acc[0][7], aa.x, w7); FFMA2(acc[1][7], aa.y, w7);
            FFMA2(acc[2][7], ab.x, w7); FFMA2(acc[3][7], ab.y, w7);
        }

        // ---- store prefetched tile into the other buffer (safe: last read
        //      of buf^1 was guarded by the previous sync) ----
        if (more) {
            const int nb = buf ^ 1;
            float* ad = &As[nb][0][0];
            ad[(akq + 0) * 64 + arow] = pa0.x; ad[(akq + 1) * 64 + arow] = pa0.y;
            ad[(akq + 2) * 64 + arow] = pa0.z; ad[(akq + 3) * 64 + arow] = pa0.w;
            ad[(akq + 4) * 64 + arow] = pa1.x; ad[(akq + 5) * 64 + arow] = pa1.y;
            ad[(akq + 6) * 64 + arow] = pa1.z; ad[(akq + 7) * 64 + arow] = pa1.w;
            if (WTRANS) {
                float* wd = &Ws[nb][0][0];
                wd[ 0 * TNN + t] = pw0.x;  wd[ 1 * TNN + t] = pw0.y;
                wd[ 2 * TNN + t] = pw0.z;  wd[ 3 * TNN + t] = pw0.w;
                wd[ 4 * TNN + t] = pw1.x;  wd[ 5 * TNN + t] = pw1.y;
                wd[ 6 * TNN + t] = pw1.z;  wd[ 7 * TNN + t] = pw1.w;
                wd[ 8 * TNN + t] = pw2.x;  wd[ 9 * TNN + t] = pw2.y;
                wd[10 * TNN + t] = pw2.z;  wd[11 * TNN + t] = pw2.w;
                wd[12 * TNN + t] = pw3.x;  wd[13 * TNN + t] = pw3.y;
                wd[14 * TNN + t] = pw3.z;  wd[15 * TNN + t] = pw3.w;
            } else {
                *(float4*)&Ws[nb][wkk][wcb +  0] = pw0;
                *(float4*)&Ws[nb][wkk][wcb +  4] = pw1;
                *(float4*)&Ws[nb][wkk][wcb +  8] = pw2;
                *(float4*)&Ws[nb][wkk][wcb + 12] = pw3;
            }
            __syncthreads();
        }
        buf ^= 1;
    }

    // ---- epilogue: two float4 groups per m-row at n0+txn*4 and n0+64+txn*4 ----
    float bv[8];
    if (bias) {
        float4 b0 = *(const float4*)(bias + n0 + txn * 4);
        float4 b1 = *(const float4*)(bias + n0 + 64 + txn * 4);
        bv[0] = b0.x; bv[1] = b0.y; bv[2] = b0.z; bv[3] = b0.w;
        bv[4] = b1.x; bv[5] = b1.y; bv[6] = b1.z; bv[7] = b1.w;
    }
    #pragma unroll
    for (int p = 0; p < 4; p++) {
        float lo[8], hi[8];
        #pragma unroll
        for (int j = 0; j < 8; j++) {
            UNPK2(lo[j], hi[j], acc[p][j]);
            if (bias) { lo[j] += bv[j]; hi[j] += bv[j]; }
            if (ACT == 1) { lo[j] = tanhf(lo[j]); hi[j] = tanhf(hi[j]); }
        }
        const int m = tym * 8 + p * 2;
        float* c0 = C + (size_t)m * N + n0 + txn * 4;
        float* c1 = c0 + N;
        float4 s;
        s.x = lo[0]; s.y = lo[1]; s.z = lo[2]; s.w = lo[3]; *(float4*)(c0)      = s;
        s.x = lo[4]; s.y = lo[5]; s.z = lo[6]; s.w = lo[7]; *(float4*)(c0 + 64) = s;
        s.x = hi[0]; s.y = hi[1]; s.z = hi[2]; s.w = hi[3]; *(float4*)(c1)      = s;
        s.x = hi[4]; s.y = hi[5]; s.z = hi[6]; s.w = hi[7]; *(float4*)(c1 + 64) = s;
    }
}

// ---------------- GEMM wrappers ----------------
__global__ void __launch_bounds__(128)
k_gru_gemm(const float* __restrict__ emb, const int* __restrict__ seq,
           const float* __restrict__ h,
           const float* __restrict__ Wih, const float* __restrict__ Whh)
{
    const int z = blockIdx.z;
    const int kb = z * 256, ke = kb + 256;
    if (blockIdx.y == 0)
        gemm_pipe_body<0, true>(emb, seq, Wih, nullptr, g_gipart[z], H, 3 * H, kb, ke);
    else
        gemm_pipe_body<0, true>(h, nullptr, Whh, nullptr, g_ghpart[z], H, 3 * H, kb, ke);
}

__global__ void __launch_bounds__(128)
k_v_gemm(const float* __restrict__ hnew, const float* __restrict__ attnW)
{
    const int z = blockIdx.z;
    gemm_pipe_body<0, false>(hnew, nullptr, attnW, nullptr, g_vpart[z],
                             H, H, z * 128, z * 128 + 128);
}

__global__ void __launch_bounds__(128)
k_concat_gemm(const float* __restrict__ catW)
{
    const int z = blockIdx.z;
    gemm_pipe_body<0, true>(g_concat_in, nullptr, catW, nullptr, g_cpart[z],
                            2 * H, H, z * 256, z * 256 + 256);
}

__global__ void __launch_bounds__(128)
k_out_gemm(const float* __restrict__ outW, const float* __restrict__ outb,
           float* __restrict__ out)
{
    gemm_pipe_body<0, true>(g_concat_out, nullptr, outW, outb, out, H, V, 0, H);
}

// ---------------- GRU gates (sums 4 K-splits) ----------------
__device__ __forceinline__ float sigmoidf_(float x) { return 1.f / (1.f + expf(-x)); }

__global__ void __launch_bounds__(256)
gru_gates_kernel(const float* __restrict__ bih, const float* __restrict__ bhh,
                 const float* __restrict__ h, float* __restrict__ hnew_out)
{
    const int idx = blockIdx.x * blockDim.x + threadIdx.x;
    const int b = idx >> 10;
    const int k = idx & (H - 1);
    const size_t o = (size_t)b * 3 * H;

    float gir = 0.f, giz = 0.f, gin = 0.f, ghr = 0.f, ghz = 0.f, ghn = 0.f;
    #pragma unroll
    for (int s = 0; s < 4; s++) {
        const float* gp = g_gipart[s] + o;
        const float* hp = g_ghpart[s] + o;
        gir += gp[k];         ghr += hp[k];
        giz += gp[H + k];     ghz += hp[H + k];
        gin += gp[2 * H + k]; ghn += hp[2 * H + k];
    }
    float r = sigmoidf_((gir + bih[k])         + (ghr + bhh[k]));
    float z = sigmoidf_((giz + bih[H + k])     + (ghz + bhh[H + k]));
    float n = tanhf((gin + bih[2 * H + k]) + r * (ghn + bhh[2 * H + k]));
    float hv = h[idx];
    float hn = (1.f - z) * n + z * hv;

    hnew_out[idx] = hn;
    g_concat_in[(size_t)b * 2 * H + k] = hn;
}

// ---------------- attention stage 1: energies ----------------
__global__ void __launch_bounds__(256)
energies_kernel(const float* __restrict__ enc)
{
    __shared__ float vs[H];
    const int b = blockIdx.y;
    const int t = threadIdx.x;
    const int warp = t >> 5, lane = t & 31;

    float4 a = {0.f, 0.f, 0.f, 0.f};
    #pragma unroll
    for (int s = 0; s < 8; s++) {
        float4 p = ((const float4*)(g_vpart[s] + (size_t)b * H))[t];
        a.x += p.x; a.y += p.y; a.z += p.z; a.w += p.w;
    }
    ((float4*)vs)[t] = a;
    __syncthreads();

    #pragma unroll
    for (int si = 0; si < 2; si++) {
        const int s = blockIdx.x * 16 + warp * 2 + si;
        const float4* row = (const float4*)(enc + ((size_t)s * B + b) * H);
        float sum = 0.f;
        #pragma unroll
        for (int i = 0; i < 8; i++) {
            float4 e = row[lane + 32 * i];
            float4 v = ((const float4*)vs)[lane + 32 * i];
            sum += e.x * v.x + e.y * v.y + e.z * v.z + e.w * v.w;
        }
        #pragma unroll
        for (int o = 16; o; o >>= 1) sum += __shfl_xor_sync(0xFFFFFFFFu, sum, o);
        if (lane == 0) g_energies[b * S + s] = sum;
    }
}

// ---------------- attention stage 2: softmax + context ----------------
__global__ void __launch_bounds__(256)
context_kernel(const float* __restrict__ enc, float* __restrict__ attn_out)
{
    __shared__ float ws[S];
    const int b = blockIdx.y;
    const int t = threadIdx.x;
    const int warp = t >> 5, lane = t & 31;

    if (warp == 0) {
        float4 e4 = ((const float4*)(g_energies + b * S))[lane];
        float m = fmaxf(fmaxf(e4.x, e4.y), fmaxf(e4.z, e4.w));
        #pragma unroll
        for (int o = 16; o; o >>= 1) m = fmaxf(m, __shfl_xor_sync(0xFFFFFFFFu, m, o));
        float4 x;
        x.x = expf(e4.x - m); x.y = expf(e4.y - m);
        x.z = expf(e4.z - m); x.w = expf(e4.w - m);
        float ss = x.x + x.y + x.z + x.w;
        #pragma unroll
        for (int o = 16; o; o >>= 1) ss += __shfl_xor_sync(0xFFFFFFFFu, ss, o);
        float inv = 1.f / ss;
        x.x *= inv; x.y *= inv; x.z *= inv; x.w *= inv;
        ((float4*)ws)[lane] = x;
        if (blockIdx.x == 0)
            ((float4*)(attn_out + (size_t)b * S))[lane] = x;
    }
    __syncthreads();

    const int h = blockIdx.x * 256 + t;
    const float* ep = enc + (size_t)b * H + h;
    float a0 = 0.f, a1 = 0.f, a2 = 0.f, a3 = 0.f;
    #pragma unroll 4
    for (int s = 0; s < S; s += 4) {
        a0 += ws[s]     * ep[(size_t)(s)     * B * H];
        a1 += ws[s + 1] * ep[(size_t)(s + 1) * B * H];
        a2 += ws[s + 2] * ep[(size_t)(s + 2) * B * H];
        a3 += ws[s + 3] * ep[(size_t)(s + 3) * B * H];
    }
    g_concat_in[(size_t)b * 2 * H + H + h] = (a0 + a1) + (a2 + a3);
}

// ---------------- concat reduce ----------------
__global__ void __launch_bounds__(256)
concat_reduce_kernel(const float* __restrict__ catb)
{
    const int idx = blockIdx.x * blockDim.x + threadIdx.x;
    const int k = idx & (H - 1);
    float s = 0.f;
    #pragma unroll
    for (int p = 0; p < 8; p++) s += g_cpart[p][idx];
    g_concat_out[idx] = tanhf(s + catb[k]);
}

// ---------------- launch ----------------
extern "C" void kernel_launch(void* const* d_in, const int* in_sizes, int n_in,
                              void* d_out, int out_size)
{
    const int*   seq   = (const int*)d_in[0];
    const float* h     = (const float*)d_in[1];
    const float* enc   = (const float*)d_in[2];
    const float* emb   = (const float*)d_in[3];
    const float* Wih   = (const float*)d_in[4];
    const float* Whh   = (const float*)d_in[5];
    const float* bih   = (const float*)d_in[6];
    const float* bhh   = (const float*)d_in[7];
    const float* attnW = (const float*)d_in[8];
    // d_in[9] = attn_b: constant across s -> cancels in softmax (and is zero)
    const float* catW  = (const float*)d_in[10];
    const float* catb  = (const float*)d_in[11];
    const float* outW  = (const float*)d_in[12];
    const float* outb  = (const float*)d_in[13];

    float* out   = (float*)d_out;
    float* hnew  = out + HNEW_OFF;
    float* attnw = out + ATTN_OFF;

    k_gru_gemm<<<dim3(3 * H / TNN, 2, 4), 128>>>(emb, seq, h, Wih, Whh);
    gru_gates_kernel<<<(B * H) / 256, 256>>>(bih, bhh, h, hnew);
    k_v_gemm<<<dim3(H / TNN, 1, 8), 128>>>(hnew, attnW);
    energies_kernel<<<dim3(8, B), 256>>>(enc);
    context_kernel<<<dim3(4, B), 256>>>(enc, attnw);
    k_concat_gemm<<<dim3(H / TNN, 1, 8), 128>>>(catW);
    concat_reduce_kernel<<<(B * H) / 256, 256>>>(catb);
    k_out_gemm<<<V / TNN, 128>>>(outW, outb, out);
}

// round 8
// speedup vs baseline: 2.9239x; 1.2138x over previous
#include <cuda_runtime.h>
#include <cuda_bf16.h>
#include <cstdint>
#include <math.h>

#define B 64
#define S 128
#define H 1024
#define V 32000

#define HNEW_OFF (B * V)
#define ATTN_OFF (B * V + B * H)

typedef unsigned long long ull;

// ---------------- packed fp32x2 (FFMA2) helpers ----------------
#define DUP2(d, x)       asm("mov.b64 %0, {%1, %1};" : "=l"(d) : "f"(x))
#define FFMA2(d, a, b)   asm("fma.rn.f32x2 %0, %1, %2, %0;" : "+l"(d) : "l"(a), "l"(b))
#define UNPK2(lo, hi, v) asm("mov.b64 {%0, %1}, %2;" : "=f"(lo), "=f"(hi) : "l"(v))

// bf16 warp MMA: d += a @ b  (m16n8k16, row.col, fp32 accum)
#define MMA_BF16(d, a, b) \
    asm volatile("mma.sync.aligned.m16n8k16.row.col.f32.bf16.bf16.f32 " \
        "{%0,%1,%2,%3}, {%4,%5,%6,%7}, {%8,%9}, {%0,%1,%2,%3};" \
        : "+f"((d)[0]), "+f"((d)[1]), "+f"((d)[2]), "+f"((d)[3]) \
        : "r"((a)[0]), "r"((a)[1]), "r"((a)[2]), "r"((a)[3]), \
          "r"((b)[0]), "r"((b)[1]))

// ---------------- device scratch ----------------
__device__ float g_gipart[4][B * 3 * H];
__device__ float g_ghpart[4][B * 3 * H];
__device__ float g_vpart[8][B * H];
__device__ float g_cpart[8][B * H];
__device__ float g_energies[B * S];
__device__ float g_concat_in[B * 2 * H];
__device__ __nv_bfloat16 g_Ahi[B * H];   // bf16 hi split of concat_out
__device__ __nv_bfloat16 g_Alo[B * H];   // bf16 lo split (residual)

// ================= FFMA2 pipelined SGEMM (GRU / v / concat) =================
#define TKK 16
#define TNN 128

template <int ACT, bool WTRANS>
__device__ __forceinline__ void gemm_pipe_body(
    const float* __restrict__ A, const int* __restrict__ gather,
    const float* __restrict__ W, const float* __restrict__ bias,
    float* __restrict__ C, int K, int N, int kb, int ke)
{
    __shared__ __align__(16) float As[2][TKK][64];
    __shared__ __align__(16) float Ws[2][TKK][TNN];

    const int n0  = blockIdx.x * TNN;
    const int t   = threadIdx.x;
    const int txn = t & 15;
    const int tym = t >> 4;

    const int arow = t >> 1;
    const int akq  = (t & 1) * 8;
    const float* Arow = (gather ? (A + (size_t)gather[arow] * K)
                                : (A + (size_t)arow * K)) + akq;

    const float* Wp;
    int wkk = 0, wcb = 0;
    if (WTRANS) {
        Wp = W + (size_t)(n0 + t) * K;
    } else {
        wkk = t >> 3;
        wcb = (t & 7) * 16;
        Wp = W + (size_t)wkk * N + n0 + wcb;
    }

    ull acc[4][8];
    #pragma unroll
    for (int p = 0; p < 4; p++)
        #pragma unroll
        for (int j = 0; j < 8; j++) acc[p][j] = 0ULL;

    float4 pa0, pa1, pw0, pw1, pw2, pw3;
    {
        const float* ap = Arow + kb;
        pa0 = *(const float4*)(ap);
        pa1 = *(const float4*)(ap + 4);
        if (WTRANS) {
            const float* wp = Wp + kb;
            pw0 = *(const float4*)(wp);      pw1 = *(const float4*)(wp + 4);
            pw2 = *(const float4*)(wp + 8);  pw3 = *(const float4*)(wp + 12);
        } else {
            const float* wp = Wp + (size_t)kb * N;
            pw0 = *(const float4*)(wp);      pw1 = *(const float4*)(wp + 4);
            pw2 = *(const float4*)(wp + 8);  pw3 = *(const float4*)(wp + 12);
        }
        float* ad = &As[0][0][0];
        ad[(akq + 0) * 64 + arow] = pa0.x; ad[(akq + 1) * 64 + arow] = pa0.y;
        ad[(akq + 2) * 64 + arow] = pa0.z; ad[(akq + 3) * 64 + arow] = pa0.w;
        ad[(akq + 4) * 64 + arow] = pa1.x; ad[(akq + 5) * 64 + arow] = pa1.y;
        ad[(akq + 6) * 64 + arow] = pa1.z; ad[(akq + 7) * 64 + arow] = pa1.w;
        if (WTRANS) {
            float* wd = &Ws[0][0][0];
            wd[ 0 * TNN + t] = pw0.x;  wd[ 1 * TNN + t] = pw0.y;
            wd[ 2 * TNN + t] = pw0.z;  wd[ 3 * TNN + t] = pw0.w;
            wd[ 4 * TNN + t] = pw1.x;  wd[ 5 * TNN + t] = pw1.y;
            wd[ 6 * TNN + t] = pw1.z;  wd[ 7 * TNN + t] = pw1.w;
            wd[ 8 * TNN + t] = pw2.x;  wd[ 9 * TNN + t] = pw2.y;
            wd[10 * TNN + t] = pw2.z;  wd[11 * TNN + t] = pw2.w;
            wd[12 * TNN + t] = pw3.x;  wd[13 * TNN + t] = pw3.y;
            wd[14 * TNN + t] = pw3.z;  wd[15 * TNN + t] = pw3.w;
        } else {
            *(float4*)&Ws[0][wkk][wcb +  0] = pw0;
            *(float4*)&Ws[0][wkk][wcb +  4] = pw1;
            *(float4*)&Ws[0][wkk][wcb +  8] = pw2;
            *(float4*)&Ws[0][wkk][wcb + 12] = pw3;
        }
    }
    __syncthreads();

    const int nIter = (ke - kb) / TKK;
    int buf = 0;
    for (int it = 0; it < nIter; it++) {
        const bool more = (it + 1 < nIter);
        if (more) {
            const int k0 = kb + (it + 1) * TKK;
            const float* ap = Arow + k0;
            pa0 = *(const float4*)(ap);
            pa1 = *(const float4*)(ap + 4);
            if (WTRANS) {
                const float* wp = Wp + k0;
                pw0 = *(const float4*)(wp);      pw1 = *(const float4*)(wp + 4);
                pw2 = *(const float4*)(wp + 8);  pw3 = *(const float4*)(wp + 12);
            } else {
                const float* wp = Wp + (size_t)k0 * N;
                pw0 = *(const float4*)(wp);      pw1 = *(const float4*)(wp + 4);
                pw2 = *(const float4*)(wp + 8);  pw3 = *(const float4*)(wp + 12);
            }
        }
        #pragma unroll
        for (int kk = 0; kk < TKK; kk++) {
            ulonglong2 aa = *(const ulonglong2*)&As[buf][kk][tym * 8];
            ulonglong2 ab = *(const ulonglong2*)&As[buf][kk][tym * 8 + 4];
            float4 wlo = *(const float4*)&Ws[buf][kk][txn * 4];
            float4 whi = *(const float4*)&Ws[buf][kk][64 + txn * 4];
            ull w0, w1, w2, w3, w4, w5, w6, w7;
            DUP2(w0, wlo.x); DUP2(w1, wlo.y); DUP2(w2, wlo.z); DUP2(w3, wlo.w);
            DUP2(w4, whi.x); DUP2(w5, whi.y); DUP2(w6, whi.z); DUP2(w7, whi.w);
            FFMA2(acc[0][0], aa.x, w0); FFMA2(acc[1][0], aa.y, w0);
            FFMA2(acc[2][0], ab.x, w0); FFMA2(acc[3][0], ab.y, w0);
            FFMA2(acc[0][1], aa.x, w1); FFMA2(acc[1][1], aa.y, w1);
            FFMA2(acc[2][1], ab.x, w1); FFMA2(acc[3][1], ab.y, w1);
            FFMA2(acc[0][2], aa.x, w2); FFMA2(acc[1][2], aa.y, w2);
            FFMA2(acc[2][2], ab.x, w2); FFMA2(acc[3][2], ab.y, w2);
            FFMA2(acc[0][3], aa.x, w3); FFMA2(acc[1][3], aa.y, w3);
            FFMA2(acc[2][3], ab.x, w3); FFMA2(acc[3][3], ab.y, w3);
            FFMA2(acc[0][4], aa.x, w4); FFMA2(acc[1][4], aa.y, w4);
            FFMA2(acc[2][4], ab.x, w4); FFMA2(acc[3][4], ab.y, w4);
            FFMA2(acc[0][5], aa.x, w5); FFMA2(acc[1][5], aa.y, w5);
            FFMA2(acc[2][5], ab.x, w5); FFMA2(acc[3][5], ab.y, w5);
            FFMA2(acc[0][6], aa.x, w6); FFMA2(acc[1][6], aa.y, w6);
            FFMA2(acc[2][6], ab.x, w6); FFMA2(acc[3][6], ab.y, w6);
            FFMA2(acc[0][7], aa.x, w7); FFMA2(acc[1][7], aa.y, w7);
            FFMA2(acc[2][7], ab.x, w7); FFMA2(acc[3][7], ab.y, w7);
        }
        if (more) {
            const int nb = buf ^ 1;
            float* ad = &As[nb][0][0];
            ad[(akq + 0) * 64 + arow] = pa0.x; ad[(akq + 1) * 64 + arow] = pa0.y;
            ad[(akq + 2) * 64 + arow] = pa0.z; ad[(akq + 3) * 64 + arow] = pa0.w;
            ad[(akq + 4) * 64 + arow] = pa1.x; ad[(akq + 5) * 64 + arow] = pa1.y;
            ad[(akq + 6) * 64 + arow] = pa1.z; ad[(akq + 7) * 64 + arow] = pa1.w;
            if (WTRANS) {
                float* wd = &Ws[nb][0][0];
                wd[ 0 * TNN + t] = pw0.x;  wd[ 1 * TNN + t] = pw0.y;
                wd[ 2 * TNN + t] = pw0.z;  wd[ 3 * TNN + t] = pw0.w;
                wd[ 4 * TNN + t] = pw1.x;  wd[ 5 * TNN + t] = pw1.y;
                wd[ 6 * TNN + t] = pw1.z;  wd[ 7 * TNN + t] = pw1.w;
                wd[ 8 * TNN + t] = pw2.x;  wd[ 9 * TNN + t] = pw2.y;
                wd[10 * TNN + t] = pw2.z;  wd[11 * TNN + t] = pw2.w;
                wd[12 * TNN + t] = pw3.x;  wd[13 * TNN + t] = pw3.y;
                wd[14 * TNN + t] = pw3.z;  wd[15 * TNN + t] = pw3.w;
            } else {
                *(float4*)&Ws[nb][wkk][wcb +  0] = pw0;
                *(float4*)&Ws[nb][wkk][wcb +  4] = pw1;
                *(float4*)&Ws[nb][wkk][wcb +  8] = pw2;
                *(float4*)&Ws[nb][wkk][wcb + 12] = pw3;
            }
            __syncthreads();
        }
        buf ^= 1;
    }

    float bv[8];
    if (bias) {
        float4 b0 = *(const float4*)(bias + n0 + txn * 4);
        float4 b1 = *(const float4*)(bias + n0 + 64 + txn * 4);
        bv[0] = b0.x; bv[1] = b0.y; bv[2] = b0.z; bv[3] = b0.w;
        bv[4] = b1.x; bv[5] = b1.y; bv[6] = b1.z; bv[7] = b1.w;
    }
    #pragma unroll
    for (int p = 0; p < 4; p++) {
        float lo[8], hi[8];
        #pragma unroll
        for (int j = 0; j < 8; j++) {
            UNPK2(lo[j], hi[j], acc[p][j]);
            if (bias) { lo[j] += bv[j]; hi[j] += bv[j]; }
            if (ACT == 1) { lo[j] = tanhf(lo[j]); hi[j] = tanhf(hi[j]); }
        }
        const int m = tym * 8 + p * 2;
        float* c0 = C + (size_t)m * N + n0 + txn * 4;
        float* c1 = c0 + N;
        float4 s;
        s.x = lo[0]; s.y = lo[1]; s.z = lo[2]; s.w = lo[3]; *(float4*)(c0)      = s;
        s.x = lo[4]; s.y = lo[5]; s.z = lo[6]; s.w = lo[7]; *(float4*)(c0 + 64) = s;
        s.x = hi[0]; s.y = hi[1]; s.z = hi[2]; s.w = hi[3]; *(float4*)(c1)      = s;
        s.x = hi[4]; s.y = hi[5]; s.z = hi[6]; s.w = hi[7]; *(float4*)(c1 + 64) = s;
    }
}

__global__ void __launch_bounds__(128)
k_gru_gemm(const float* __restrict__ emb, const int* __restrict__ seq,
           const float* __restrict__ h,
           const float* __restrict__ Wih, const float* __restrict__ Whh)
{
    const int z = blockIdx.z;
    const int kb = z * 256, ke = kb + 256;
    if (blockIdx.y == 0)
        gemm_pipe_body<0, true>(emb, seq, Wih, nullptr, g_gipart[z], H, 3 * H, kb, ke);
    else
        gemm_pipe_body<0, true>(h, nullptr, Whh, nullptr, g_ghpart[z], H, 3 * H, kb, ke);
}

__global__ void __launch_bounds__(128)
k_v_gemm(const float* __restrict__ hnew, const float* __restrict__ attnW)
{
    const int z = blockIdx.z;
    gemm_pipe_body<0, false>(hnew, nullptr, attnW, nullptr, g_vpart[z],
                             H, H, z * 128, z * 128 + 128);
}

__global__ void __launch_bounds__(128)
k_concat_gemm(const float* __restrict__ catW)
{
    const int z = blockIdx.z;
    gemm_pipe_body<0, true>(g_concat_in, nullptr, catW, nullptr, g_cpart[z],
                            2 * H, H, z * 256, z * 256 + 256);
}

// ================= GRU gates =================
__device__ __forceinline__ float sigmoidf_(float x) { return 1.f / (1.f + expf(-x)); }

__global__ void __launch_bounds__(256)
gru_gates_kernel(const float* __restrict__ bih, const float* __restrict__ bhh,
                 const float* __restrict__ h, float* __restrict__ hnew_out)
{
    const int idx = blockIdx.x * blockDim.x + threadIdx.x;
    const int b = idx >> 10;
    const int k = idx & (H - 1);
    const size_t o = (size_t)b * 3 * H;

    float gir = 0.f, giz = 0.f, gin = 0.f, ghr = 0.f, ghz = 0.f, ghn = 0.f;
    #pragma unroll
    for (int s = 0; s < 4; s++) {
        const float* gp = g_gipart[s] + o;
        const float* hp = g_ghpart[s] + o;
        gir += gp[k];         ghr += hp[k];
        giz += gp[H + k];     ghz += hp[H + k];
        gin += gp[2 * H + k]; ghn += hp[2 * H + k];
    }
    float r = sigmoidf_((gir + bih[k])         + (ghr + bhh[k]));
    float z = sigmoidf_((giz + bih[H + k])     + (ghz + bhh[H + k]));
    float n = tanhf((gin + bih[2 * H + k]) + r * (ghn + bhh[2 * H + k]));
    float hv = h[idx];
    float hn = (1.f - z) * n + z * hv;

    hnew_out[idx] = hn;
    g_concat_in[(size_t)b * 2 * H + k] = hn;
}

// ================= attention =================
__global__ void __launch_bounds__(256)
energies_kernel(const float* __restrict__ enc)
{
    __shared__ float vs[H];
    const int b = blockIdx.y;
    const int t = threadIdx.x;
    const int warp = t >> 5, lane = t & 31;

    float4 a = {0.f, 0.f, 0.f, 0.f};
    #pragma unroll
    for (int s = 0; s < 8; s++) {
        float4 p = ((const float4*)(g_vpart[s] + (size_t)b * H))[t];
        a.x += p.x; a.y += p.y; a.z += p.z; a.w += p.w;
    }
    ((float4*)vs)[t] = a;
    __syncthreads();

    #pragma unroll
    for (int si = 0; si < 2; si++) {
        const int s = blockIdx.x * 16 + warp * 2 + si;
        const float4* row = (const float4*)(enc + ((size_t)s * B + b) * H);
        float sum = 0.f;
        #pragma unroll
        for (int i = 0; i < 8; i++) {
            float4 e = row[lane + 32 * i];
            float4 v = ((const float4*)vs)[lane + 32 * i];
            sum += e.x * v.x + e.y * v.y + e.z * v.z + e.w * v.w;
        }
        #pragma unroll
        for (int o = 16; o; o >>= 1) sum += __shfl_xor_sync(0xFFFFFFFFu, sum, o);
        if (lane == 0) g_energies[b * S + s] = sum;
    }
}

__global__ void __launch_bounds__(256)
context_kernel(const float* __restrict__ enc, float* __restrict__ attn_out)
{
    __shared__ float ws[S];
    const int b = blockIdx.y;
    const int t = threadIdx.x;
    const int warp = t >> 5, lane = t & 31;

    if (warp == 0) {
        float4 e4 = ((const float4*)(g_energies + b * S))[lane];
        float m = fmaxf(fmaxf(e4.x, e4.y), fmaxf(e4.z, e4.w));
        #pragma unroll
        for (int o = 16; o; o >>= 1) m = fmaxf(m, __shfl_xor_sync(0xFFFFFFFFu, m, o));
        float4 x;
        x.x = expf(e4.x - m); x.y = expf(e4.y - m);
        x.z = expf(e4.z - m); x.w = expf(e4.w - m);
        float ss = x.x + x.y + x.z + x.w;
        #pragma unroll
        for (int o = 16; o; o >>= 1) ss += __shfl_xor_sync(0xFFFFFFFFu, ss, o);
        float inv = 1.f / ss;
        x.x *= inv; x.y *= inv; x.z *= inv; x.w *= inv;
        ((float4*)ws)[lane] = x;
        if (blockIdx.x == 0)
            ((float4*)(attn_out + (size_t)b * S))[lane] = x;
    }
    __syncthreads();

    const int h = blockIdx.x * 256 + t;
    const float* ep = enc + (size_t)b * H + h;
    float a0 = 0.f, a1 = 0.f, a2 = 0.f, a3 = 0.f;
    #pragma unroll 4
    for (int s = 0; s < S; s += 4) {
        a0 += ws[s]     * ep[(size_t)(s)     * B * H];
        a1 += ws[s + 1] * ep[(size_t)(s + 1) * B * H];
        a2 += ws[s + 2] * ep[(size_t)(s + 2) * B * H];
        a3 += ws[s + 3] * ep[(size_t)(s + 3) * B * H];
    }
    g_concat_in[(size_t)b * 2 * H + H + h] = (a0 + a1) + (a2 + a3);
}

// ================= concat reduce -> tanh -> bf16 hi/lo split =================
__global__ void __launch_bounds__(256)
concat_reduce_kernel(const float* __restrict__ catb)
{
    const int idx = blockIdx.x * blockDim.x + threadIdx.x;
    const int k = idx & (H - 1);
    float s = 0.f;
    #pragma unroll
    for (int p = 0; p < 8; p++) s += g_cpart[p][idx];
    float val = tanhf(s + catb[k]);
    __nv_bfloat16 hi = __float2bfloat16_rn(val);
    float lof = val - __bfloat162float(hi);
    g_Ahi[idx] = hi;
    g_Alo[idx] = __float2bfloat16_rn(lof);
}

// ================= out GEMM via warp-level bf16 mma.sync =================
// out[64, 32000] = A @ outW^T + outb, 3-term bf16 split:
//   A_hi W_hi + A_hi W_lo + A_lo W_hi   (A_lo W_lo ~ 2^-18, dropped)
// 250 CTAs x (M=64, N=128); 8 warps (2 m x 4 n), each 32x32;
// K staged in 64-chunks, fp32 W converted to bf16 hi/lo in regs.

#define PADK   72                       // bf16 row stride (conflict-free)
#define AS_HI  0
#define AS_LO  (64 * PADK * 2)          // 9216
#define WS_HI  (2 * 64 * PADK * 2)      // 18432
#define WS_LO  (WS_HI + 128 * PADK * 2) // 36864
#define OSTAGE (WS_LO + 128 * PADK * 2) // 55296 per stage
#define OBIAS  (2 * OSTAGE)             // 110592
#define OUT_SMEM (OBIAS + 512)

__device__ __forceinline__ void cvt_hi_lo(float x, float y, uint32_t& h, uint32_t& l)
{
    asm("cvt.rn.bf16x2.f32 %0, %1, %2;" : "=r"(h) : "f"(y), "f"(x));  // low=x, high=y
    float hx = __uint_as_float(h << 16);
    float hy = __uint_as_float(h & 0xFFFF0000u);
    float lx = x - hx, ly = y - hy;
    asm("cvt.rn.bf16x2.f32 %0, %1, %2;" : "=r"(l) : "f"(ly), "f"(lx));
}

__device__ __forceinline__ uint32_t lds_u32(const __nv_bfloat16* p, int r, int k)
{
    return *(const uint32_t*)(p + r * PADK + k);
}

__global__ void __launch_bounds__(256, 1)
k_out_mma(const float* __restrict__ outW, const float* __restrict__ outb,
          float* __restrict__ out)
{
    extern __shared__ __align__(16) char smem[];
    const int t = threadIdx.x;
    const int lane = t & 31, wid = t >> 5;
    const int wr = wid >> 2, wc = wid & 3;      // warp 2x4 grid
    const int gid = lane >> 2, tk = lane & 3;
    const int n0 = blockIdx.x * 128;

    if (t < 128) ((float*)(smem + OBIAS))[t] = outb[n0 + t];

    // prefetch source pointers
    const int w_r = t >> 1, w_kh = t & 1;                 // W: row, k-half(32)
    const float* wsrc = outW + (size_t)(n0 + w_r) * H + w_kh * 32;
    const int a_r = t >> 2, a_seg = (t & 3) * 16;         // A: row, 16-elt seg
    const __nv_bfloat16* ahsrc = g_Ahi + (size_t)a_r * H + a_seg;
    const __nv_bfloat16* alsrc = g_Alo + (size_t)a_r * H + a_seg;

    float acc[2][4][4];
    #pragma unroll
    for (int i = 0; i < 2; i++)
        #pragma unroll
        for (int j = 0; j < 4; j++)
            #pragma unroll
            for (int c = 0; c < 4; c++) acc[i][j][c] = 0.f;

    float4 wp[8];
    uint4 aph[2], apl[2];

    // ---- stage loader (regs) ----
    auto load_regs = [&](int s) {
        const int kb = s * 64;
        const float* wv = wsrc + kb;
        #pragma unroll
        for (int i = 0; i < 8; i++) wp[i] = *(const float4*)(wv + i * 4);
        aph[0] = *(const uint4*)(ahsrc + kb);
        aph[1] = *(const uint4*)(ahsrc + kb + 8);
        apl[0] = *(const uint4*)(alsrc + kb);
        apl[1] = *(const uint4*)(alsrc + kb + 8);
    };
    // ---- regs -> smem (with W fp32->bf16 hi/lo conversion) ----
    auto store_stage = [&](int buf) {
        char* sb = smem + buf * OSTAGE;
        {
            uint4* ah = (uint4*)(sb + AS_HI + (a_r * PADK + a_seg) * 2);
            ah[0] = aph[0]; ah[1] = aph[1];
            uint4* al = (uint4*)(sb + AS_LO + (a_r * PADK + a_seg) * 2);
            al[0] = apl[0]; al[1] = apl[1];
        }
        {
            uint32_t hh[16], ll[16];
            #pragma unroll
            for (int j = 0; j < 8; j++) {
                cvt_hi_lo(wp[j].x, wp[j].y, hh[j * 2],     ll[j * 2]);
                cvt_hi_lo(wp[j].z, wp[j].w, hh[j * 2 + 1], ll[j * 2 + 1]);
            }
            uint4* wh = (uint4*)(sb + WS_HI + (w_r * PADK + w_kh * 32) * 2);
            uint4* wl = (uint4*)(sb + WS_LO + (w_r * PADK + w_kh * 32) * 2);
            #pragma unroll
            for (int i = 0; i < 4; i++) {
                wh[i] = make_uint4(hh[i*4], hh[i*4+1], hh[i*4+2], hh[i*4+3]);
                wl[i] = make_uint4(ll[i*4], ll[i*4+1], ll[i*4+2], ll[i*4+3]);
            }
        }
    };
    // ---- compute one 64-K stage ----
    auto compute = [&](int buf) {
        const char* sb = smem + buf * OSTAGE;
        const __nv_bfloat16* AH = (const __nv_bfloat16*)(sb + AS_HI);
        const __nv_bfloat16* AL = (const __nv_bfloat16*)(sb + AS_LO);
        const __nv_bfloat16* WH = (const __nv_bfloat16*)(sb + WS_HI);
        const __nv_bfloat16* WL = (const __nv_bfloat16*)(sb + WS_LO);
        #pragma unroll
        for (int ks = 0; ks < 4; ks++) {
            const int kc = ks * 16 + tk * 2;
            uint32_t ah[2][4], al[2][4];
            #pragma unroll
            for (int mi = 0; mi < 2; mi++) {
                const int r0 = wr * 32 + mi * 16 + gid;
                ah[mi][0] = lds_u32(AH, r0,     kc);
                ah[mi][1] = lds_u32(AH, r0 + 8, kc);
                ah[mi][2] = lds_u32(AH, r0,     kc + 8);
                ah[mi][3] = lds_u32(AH, r0 + 8, kc + 8);
                al[mi][0] = lds_u32(AL, r0,     kc);
                al[mi][1] = lds_u32(AL, r0 + 8, kc);
                al[mi][2] = lds_u32(AL, r0,     kc + 8);
                al[mi][3] = lds_u32(AL, r0 + 8, kc + 8);
            }
            #pragma unroll
            for (int nj = 0; nj < 4; nj++) {
                const int n = wc * 32 + nj * 8 + gid;
                uint32_t bh[2] = { lds_u32(WH, n, kc), lds_u32(WH, n, kc + 8) };
                uint32_t bl[2] = { lds_u32(WL, n, kc), lds_u32(WL, n, kc + 8) };
                #pragma unroll
                for (int mi = 0; mi < 2; mi++) {
                    MMA_BF16(acc[mi][nj], ah[mi], bh);
                    MMA_BF16(acc[mi][nj], ah[mi], bl);
                    MMA_BF16(acc[mi][nj], al[mi], bh);
                }
            }
        }
    };

    load_regs(0);
    store_stage(0);
    __syncthreads();
    for (int s = 0; s < 16; s++) {
        if (s < 15) load_regs(s + 1);
        compute(s & 1);
        if (s < 15) {
            store_stage((s & 1) ^ 1);
            __syncthreads();
        }
    }

    // epilogue
    const float* sbias = (const float*)(smem + OBIAS);
    #pragma unroll
    for (int mi = 0; mi < 2; mi++) {
        const int m = wr * 32 + mi * 16 + gid;
        #pragma unroll
        for (int nj = 0; nj < 4; nj++) {
            const int nn = wc * 32 + nj * 8 + tk * 2;
            const float b0 = sbias[nn], b1 = sbias[nn + 1];
            float2 v0 = { acc[mi][nj][0] + b0, acc[mi][nj][1] + b1 };
            float2 v1 = { acc[mi][nj][2] + b0, acc[mi][nj][3] + b1 };
            *(float2*)(out + (size_t)m * V + n0 + nn)       = v0;
            *(float2*)(out + (size_t)(m + 8) * V + n0 + nn) = v1;
        }
    }
}

// ================= launch =================
extern "C" void kernel_launch(void* const* d_in, const int* in_sizes, int n_in,
                              void* d_out, int out_size)
{
    const int*   seq   = (const int*)d_in[0];
    const float* h     = (const float*)d_in[1];
    const float* enc   = (const float*)d_in[2];
    const float* emb   = (const float*)d_in[3];
    const float* Wih   = (const float*)d_in[4];
    const float* Whh   = (const float*)d_in[5];
    const float* bih   = (const float*)d_in[6];
    const float* bhh   = (const float*)d_in[7];
    const float* attnW = (const float*)d_in[8];
    // d_in[9] = attn_b: constant across s -> cancels in softmax (and is zero)
    const float* catW  = (const float*)d_in[10];
    const float* catb  = (const float*)d_in[11];
    const float* outW  = (const float*)d_in[12];
    const float* outb  = (const float*)d_in[13];

    float* out   = (float*)d_out;
    float* hnew  = out + HNEW_OFF;
    float* attnw = out + ATTN_OFF;

    cudaFuncSetAttribute(k_out_mma, cudaFuncAttributeMaxDynamicSharedMemorySize, OUT_SMEM);

    k_gru_gemm<<<dim3(3 * H / TNN, 2, 4), 128>>>(emb, seq, h, Wih, Whh);
    gru_gates_kernel<<<(B * H) / 256, 256>>>(bih, bhh, h, hnew);
    k_v_gemm<<<dim3(H / TNN, 1, 8), 128>>>(hnew, attnW);
    energies_kernel<<<dim3(8, B), 256>>>(enc);
    context_kernel<<<dim3(4, B), 256>>>(enc, attnw);
    k_concat_gemm<<<dim3(H / TNN, 1, 8), 128>>>(catW);
    concat_reduce_kernel<<<(B * H) / 256, 256>>>(catb);
    k_out_mma<<<V / 128, 256, OUT_SMEM>>>(outW, outb, out);
}